// round 16
// baseline (speedup 1.0000x reference)
#include <cuda_runtime.h>
#include <math.h>

#define B_IMG 32
#define KGT   16
#define NCLS  80
#define NPRI  8525
#define NSLOT 45

#define ASSIGN_BLKS 32
#define S0_BLKS     1152
#define NBLK_TOT    (ASSIGN_BLKS + S0_BLKS)   // 1184
#define NTHR        256

// deterministic partial-sum scratch
__device__ float g_part[S0_BLKS];   // S0 focal base partials
__device__ float g_img[B_IMG][4];   // per-image: corr, npos, locv, vsum
__device__ unsigned int g_done = 0; // last-block-done counter (self-resetting)

__device__ __forceinline__ float rcp_a(float x) {
    float r; asm("rcp.approx.f32 %0, %1;" : "=f"(r) : "f"(x)); return r;
}
__device__ __forceinline__ float ex2_a(float x) {
    float r; asm("ex2.approx.f32 %0, %1;" : "=f"(r) : "f"(x)); return r;
}

// sigmoid(x)^2 * softplus(x)  (t=0 focal negative term; 0.75 applied to the
// block partial). ONLY 2 MUFU per element (ex2 + rcp); ln(1+u) for
// u = e^{-|x|} in [0,1] via degree-6 Chebyshev-minimax polynomial
// (|err| <= 1.6e-6, oscillating). softplus(x) = max(x,0) + ln(1+u);
// sigma(x)^2 = pa^2 * (x>=0 ? 1 : u^2) with pa = 1/(1+u).
__device__ __forceinline__ float s0t(float x) {
    float u  = ex2_a(fabsf(x) * -1.44269504088896340736f);  // e^{-|x|}
    float pa = rcp_a(1.0f + u);                             // sigmoid(|x|)
    float P  = fmaf(u, -0.017414976f, 0.082693760f);        // ln(1+u) poly
    P = fmaf(u, P, -0.190356576f);
    P = fmaf(u, P,  0.315747784f);
    P = fmaf(u, P, -0.497372992f);
    P = fmaf(u, P,  0.999847620f);
    P = fmaf(u, P,  1.475e-6f);
    float sp = fmaxf(x, 0.0f) + P;                          // softplus(x)
    float s  = (x >= 0.0f) ? 1.0f : u * u;
    float q  = pa * pa;
    return (q * s) * sp;
}

__device__ __forceinline__ float s0t4(float4 v) {
    return (s0t(v.x) + s0t(v.y)) + (s0t(v.z) + s0t(v.w));
}

__device__ __forceinline__ bool lexless(float a, int ia, float b, int ib) {
    return (a < b) || (a == b && ia < ib);
}

__global__ void k_main(const float* __restrict__ locs,
                       const float* __restrict__ scores,
                       const float* __restrict__ boxes,
                       const int* __restrict__ labels,
                       float* __restrict__ out) {
    __shared__ float s_r[8];
    __shared__ float s_img[4];
    __shared__ int   s_last;

    int tid = threadIdx.x, lane = tid & 31, warp = tid >> 5;

    if (blockIdx.x >= ASSIGN_BLKS) {
        // ==== streaming S0: batch-8 independent loads ====
        const float4* s4 = (const float4*)scores;
        const int N4  = (B_IMG * NPRI * NCLS) / 4;     // 5,456,000
        const int STR = S0_BLKS * NTHR;                // 294,912
        int sb = blockIdx.x - ASSIGN_BLKS;

        float a0 = 0.0f, a1 = 0.0f, a2 = 0.0f, a3 = 0.0f;
        int i = sb * NTHR + tid;
        for (; i + 7 * STR < N4; i += 8 * STR) {       // 8 independent loads
            float4 v0 = s4[i];
            float4 v1 = s4[i + STR];
            float4 v2 = s4[i + 2 * STR];
            float4 v3 = s4[i + 3 * STR];
            float4 v4 = s4[i + 4 * STR];
            float4 v5 = s4[i + 5 * STR];
            float4 v6 = s4[i + 6 * STR];
            float4 v7 = s4[i + 7 * STR];
            a0 += s0t4(v0) + s0t4(v4);
            a1 += s0t4(v1) + s0t4(v5);
            a2 += s0t4(v2) + s0t4(v6);
            a3 += s0t4(v3) + s0t4(v7);
        }
        for (; i < N4; i += STR) a0 += s0t4(s4[i]);
        float acc = (a0 + a1) + (a2 + a3);
#pragma unroll
        for (int off = 16; off; off >>= 1)
            acc += __shfl_down_sync(0xFFFFFFFFu, acc, off);
        if (lane == 0) s_r[warp] = acc;
        __syncthreads();
        if (tid == 0) {
            float t = 0.0f;
            for (int w = 0; w < 8; w++) t += s_r[w];
            g_part[sb] = 0.75f * t;
        }
    } else {
        // ================= assignment: one block per image =================
        __shared__ float s_ctab[155];
        __shared__ float s_box[KGT][4];
        __shared__ float s_gcx[KGT], s_gcy[KGT], s_area[KGT];
        __shared__ int   s_lab[KGT];
        __shared__ int   s_tidx[KGT][NSLOT];
        __shared__ float s_pov[KGT][NSLOT];
        __shared__ unsigned char s_ins[KGT][NSLOT];
        __shared__ float s_thr[KGT];
        __shared__ float s_red[2][4];

        const int   f_[5]    = {80, 40, 20, 10, 5};
        const int   coff_[5] = {0, 80, 120, 140, 150};
        const float sl_[5]   = {0.06f, 0.12f, 0.24f, 0.48f, 0.72f};
        const int   sp_[5]   = {0, 6400, 8000, 8400, 8500};

        int img = blockIdx.x;

        if (tid < KGT) {
            float x0 = boxes[(img * KGT + tid) * 4 + 0];
            float y0 = boxes[(img * KGT + tid) * 4 + 1];
            float x1 = boxes[(img * KGT + tid) * 4 + 2];
            float y1 = boxes[(img * KGT + tid) * 4 + 3];
            s_box[tid][0] = x0; s_box[tid][1] = y0; s_box[tid][2] = x1; s_box[tid][3] = y1;
            s_gcx[tid] = (x0 + x1) / 2.0f;
            s_gcy[tid] = (y0 + y1) / 2.0f;
            s_area[tid] = (x1 - x0) * (y1 - y0);
            s_lab[tid] = labels[img * KGT + tid];
        }
        // analytic priors, bit-identical to (arange+0.5)/f in fp32
        for (int t = tid; t < 155; t += NTHR) {
            int i2; float fv;
            if      (t < 80)  { i2 = t;       fv = 80.0f; }
            else if (t < 120) { i2 = t - 80;  fv = 40.0f; }
            else if (t < 140) { i2 = t - 120; fv = 20.0f; }
            else if (t < 150) { i2 = t - 140; fv = 10.0f; }
            else              { i2 = t - 150; fv = 5.0f;  }
            s_ctab[t] = ((float)i2 + 0.5f) / fv;
        }
        __syncthreads();

        // phase B: one thread per (GT, level): windowed top-9 + IoU
        if (tid < KGT * 5) {
            int k = tid / 5, l = tid - k * 5;
            int F = f_[l];
            const float* ct = s_ctab + coff_[l];
            float gcx = s_gcx[k], gcy = s_gcy[k];
            int W = (F < 6) ? F : 6;

            float ux = gcx * (float)F - 0.5f;
            int ix0 = (int)floorf(ux);
            int lx = ix0 - 2; if (lx < 0) lx = 0; if (lx > F - W) lx = F - W;
            float uy = gcy * (float)F - 0.5f;
            int iy0 = (int)floorf(uy);
            int ly = iy0 - 2; if (ly < 0) ly = 0; if (ly > F - W) ly = F - W;

            float ld[9]; int li[9];
#pragma unroll
            for (int q = 0; q < 9; q++) { ld[q] = INFINITY; li[q] = 0x7FFFFFFF; }
            for (int jy = ly; jy < ly + W; jy++) {
                float dy = gcy - ct[jy];
                for (int jx = lx; jx < lx + W; jx++) {
                    float dx = gcx - ct[jx];
                    float d  = sqrtf(dx * dx + dy * dy);
                    int p = jy * F + jx;
                    if (lexless(d, p, ld[8], li[8])) {
                        ld[8] = d; li[8] = p;
#pragma unroll
                        for (int q = 8; q > 0; q--) {
                            if (lexless(ld[q], li[q], ld[q - 1], li[q - 1])) {
                                float td = ld[q]; ld[q] = ld[q - 1]; ld[q - 1] = td;
                                int   ti = li[q]; li[q] = li[q - 1]; li[q - 1] = ti;
                            }
                        }
                    }
                }
            }
            float gx0 = s_box[k][0], gy0 = s_box[k][1];
            float gx1 = s_box[k][2], gy1 = s_box[k][3];
            float areaA = s_area[k];
            float S = sl_[l];
            float h = S / 2.0f;
#pragma unroll
            for (int j = 0; j < 9; j++) {
                int p = li[j];
                s_tidx[k][l * 9 + j] = p;
                int iy = p / F, ix = p - iy * F;
                float cx = ct[ix], cy = ct[iy];
                float px0 = cx - h, py0 = cy - h, px1 = cx + h, py1 = cy + h;
                float ltx = fmaxf(gx0, px0), lty = fmaxf(gy0, py0);
                float rbx = fminf(gx1, px1), rby = fminf(gy1, py1);
                float ww = fmaxf(rbx - ltx, 0.0f), hh = fmaxf(rby - lty, 0.0f);
                float inter = ww * hh;
                float areaB = (px1 - px0) * (py1 - py0);
                s_pov[k][l * 9 + j] = inter / (areaA + areaB - inter);
                s_ins[k][l * 9 + j] = (gx0 < cx) && (cx < gx1) && (gy0 < cy) && (cy < gy1);
            }
        }
        __syncthreads();

        // phase C: ATSS threshold per GT
        if (tid < KGT) {
            float sum = 0.0f;
            for (int t = 0; t < NSLOT; t++) sum += s_pov[tid][t];
            float mean = sum / 45.0f;
            float ss = 0.0f;
            for (int t = 0; t < NSLOT; t++) { float dv = s_pov[tid][t] - mean; ss += dv * dv; }
            s_thr[tid] = mean + sqrtf(ss / 44.0f);
        }
        __syncthreads();

        // phase D: per-slot argmax over GTs, focal correction, decode+CIoU
        float corr = 0.0f, npos = 0.0f, locv = 0.0f, vsum = 0.0f;
        if (tid < NSLOT) {
            int l = tid / 9, j = tid - l * 9;
            float best = (s_ins[0][tid] && s_pov[0][tid] > s_thr[0]) ? s_pov[0][tid] : 0.0f;
            int bk = 0;
#pragma unroll
            for (int k2 = 1; k2 < KGT; k2++) {
                float m = (s_ins[k2][tid] && s_pov[k2][tid] > s_thr[k2]) ? s_pov[k2][tid] : 0.0f;
                if (m > best) { best = m; bk = k2; }
            }
            if (best > 0.0f) {
                vsum = 1.0f;
                int lab = s_lab[bk];
                npos = 1.0f;
                int gpos = sp_[l] + j;
                float x  = scores[((long)img * NPRI + gpos) * NCLS + (lab - 1)];
                float ax = fabsf(x);
                float em = expf(-ax);
                float l1 = log1pf(em);
                float spp = fmaxf(-x, 0.0f) + l1;   // softplus(-x)
                float spn = fmaxf( x, 0.0f) + l1;   // softplus(x)
                float r  = 1.0f / (1.0f + em);
                float pp = (x >= 0.0f) ? r : em * r;
                float qq = 1.0f - pp;
                corr = 0.25f * qq * qq * spp - 0.75f * pp * pp * spn;
                int pidx = s_tidx[bk][tid];
                int gp   = sp_[l] + pidx;
                const float* g = locs + ((long)img * NPRI + gp) * 4;
                int F = f_[l]; float S = sl_[l];
                int iy = pidx / F, ix = pidx - iy * F;
                float cx = s_ctab[coff_[l] + ix], cy = s_ctab[coff_[l] + iy];
                float pcx = (g[0] * S) / 10.0f + cx;
                float pcy = (g[1] * S) / 10.0f + cy;
                float pw  = expf(g[2] / 5.0f) * S;
                float ph  = expf(g[3] / 5.0f) * S;
                float qx0 = pcx - pw / 2.0f, qy0 = pcy - ph / 2.0f;
                float qx1 = pcx + pw / 2.0f, qy1 = pcy + ph / 2.0f;
                float t0 = s_box[bk][0], t1 = s_box[bk][1];
                float t2 = s_box[bk][2], t3 = s_box[bk][3];
                float w1 = qx1 - qx0, h1 = qy1 - qy0;
                float w2 = t2 - t0,   h2 = t3 - t1;
                float ltx = fmaxf(qx0, t0), lty = fmaxf(qy0, t1);
                float rbx = fminf(qx1, t2), rby = fminf(qy1, t3);
                float iw = fmaxf(rbx - ltx, 0.0f), ih = fmaxf(rby - lty, 0.0f);
                float inter = iw * ih;
                float uni = w1 * h1 + w2 * h2 - inter;
                float iou = inter / uni;
                float c1x = (qx0 + qx1) / 2.0f, c1y = (qy0 + qy1) / 2.0f;
                float c2x = (t0 + t2) / 2.0f,  c2y = (t1 + t3) / 2.0f;
                float dx = c1x - c2x, dy = c1y - c2y;
                float rho2 = dx * dx + dy * dy;
                float ex0 = fminf(qx0, t0), ey0 = fminf(qy0, t1);
                float ex1 = fmaxf(qx1, t2), ey1 = fmaxf(qy1, t3);
                float ddx = ex1 - ex0, ddy = ey1 - ey0;
                float cdiag = ddx * ddx + ddy * ddy;
                float at = atanf(w2 / h2) - atanf(w1 / h1);
                float v  = 0.40528473456935108f * at * at;   // 4/pi^2 (fp32)
                float alpha = v / (1.0f - iou + v);
                float ci = iou - rho2 / cdiag - alpha * v;
                ci = fminf(fmaxf(ci, -1.0f), 1.0f);
                locv = 1.0f - ci;
            }
        }
        if (warp < 2) {   // slots live in warps 0 and 1 only
#pragma unroll
            for (int off = 16; off; off >>= 1) {
                corr += __shfl_down_sync(0xFFFFFFFFu, corr, off);
                npos += __shfl_down_sync(0xFFFFFFFFu, npos, off);
                locv += __shfl_down_sync(0xFFFFFFFFu, locv, off);
                vsum += __shfl_down_sync(0xFFFFFFFFu, vsum, off);
            }
            if (lane == 0) {
                s_red[warp][0] = corr; s_red[warp][1] = npos;
                s_red[warp][2] = locv; s_red[warp][3] = vsum;
            }
        }
        __syncthreads();
        if (tid == 0) {
            g_img[img][0] = s_red[0][0] + s_red[1][0];
            g_img[img][1] = s_red[0][1] + s_red[1][1];
            g_img[img][2] = s_red[0][2] + s_red[1][2];
            g_img[img][3] = s_red[0][3] + s_red[1][3];
        }
    }

    // ---- last-block-done: deterministic fixed-order final reduction ----
    __threadfence();
    __syncthreads();
    if (tid == 0) {
        unsigned int v = atomicAdd(&g_done, 1u);
        s_last = (v == NBLK_TOT - 1) ? 1 : 0;
    }
    __syncthreads();
    if (s_last) {
        __threadfence();
        float acc2 = 0.0f;
        for (int j = tid; j < S0_BLKS; j += NTHR) acc2 += g_part[j];
#pragma unroll
        for (int off = 16; off; off >>= 1)
            acc2 += __shfl_down_sync(0xFFFFFFFFu, acc2, off);
        if (lane == 0) s_r[warp] = acc2;
        if (warp == 1) {   // reduce the 32 per-image 4-vectors (fixed order)
            float c0 = g_img[lane][0], c1 = g_img[lane][1];
            float c2 = g_img[lane][2], c3 = g_img[lane][3];
#pragma unroll
            for (int off = 16; off; off >>= 1) {
                c0 += __shfl_down_sync(0xFFFFFFFFu, c0, off);
                c1 += __shfl_down_sync(0xFFFFFFFFu, c1, off);
                c2 += __shfl_down_sync(0xFFFFFFFFu, c2, off);
                c3 += __shfl_down_sync(0xFFFFFFFFu, c3, off);
            }
            if (lane == 0) {
                s_img[0] = c0; s_img[1] = c1; s_img[2] = c2; s_img[3] = c3;
            }
        }
        __syncthreads();
        if (tid == 0) {
            float s0 = 0.0f;
            for (int w = 0; w < 8; w++) s0 += s_r[w];
            float conf = (s0 + s_img[0]) / s_img[1];
            float loc  = s_img[2] / fmaxf(s_img[3], 1.0f);
            out[0] = conf + loc;
            g_done = 0;   // self-reset for next graph replay
        }
    }
}

extern "C" void kernel_launch(void* const* d_in, const int* in_sizes, int n_in,
                              void* d_out, int out_size) {
    const float* locs   = (const float*)d_in[0];
    const float* scores = (const float*)d_in[1];
    const float* boxes  = (const float*)d_in[2];
    const int*   labels = (const int*)d_in[3];
    float* out = (float*)d_out;
    (void)in_sizes; (void)n_in; (void)out_size;

    k_main<<<NBLK_TOT, NTHR>>>(locs, scores, boxes, labels, out);
}

// round 17
// speedup vs baseline: 1.1260x; 1.1260x over previous
#include <cuda_runtime.h>
#include <math.h>

#define B_IMG 32
#define KGT   16
#define NCLS  80
#define NPRI  8525
#define NSLOT 45

#define ASSIGN_BLKS 32
#define S0_BLKS     1152
#define NBLK_TOT    (ASSIGN_BLKS + S0_BLKS)   // 1184
#define NTHR        256

typedef unsigned long long ull;

// deterministic partial-sum scratch
__device__ float g_part[S0_BLKS];   // S0 focal base partials
__device__ float g_img[B_IMG][4];   // per-image: corr, npos, locv, vsum
__device__ unsigned int g_done = 0; // last-block-done counter (self-resetting)

__device__ __forceinline__ float ex2_a(float x) {
    float r; asm("ex2.approx.f32 %0, %1;" : "=f"(r) : "f"(x)); return r;
}
__device__ __forceinline__ ull pk2(float lo, float hi) {
    ull r; asm("mov.b64 %0, {%1, %2};" : "=l"(r) : "f"(lo), "f"(hi)); return r;
}
__device__ __forceinline__ void upk2(float& lo, float& hi, ull p) {
    asm("mov.b64 {%0, %1}, %2;" : "=f"(lo), "=f"(hi) : "l"(p));
}
__device__ __forceinline__ ull fma2(ull a, ull b, ull c) {
    ull d; asm("fma.rn.f32x2 %0, %1, %2, %3;" : "=l"(d) : "l"(a), "l"(b), "l"(c)); return d;
}
__device__ __forceinline__ ull add2(ull a, ull b) {
    ull d; asm("add.rn.f32x2 %0, %1, %2;" : "=l"(d) : "l"(a), "l"(b)); return d;
}

// packed poly coefficients for ln(1+u), u in [0,1] (validated in R15: overall
// rel_err 1.14e-7, same as libm path)
struct PC { ull c6, c5, c4, c3, c2, c1, c0; };
__device__ __forceinline__ PC make_pc() {
    PC k;
    k.c6 = pk2(-0.017414976f, -0.017414976f);
    k.c5 = pk2( 0.082693760f,  0.082693760f);
    k.c4 = pk2(-0.190356576f, -0.190356576f);
    k.c3 = pk2( 0.315747784f,  0.315747784f);
    k.c2 = pk2(-0.497372992f, -0.497372992f);
    k.c1 = pk2( 0.999847620f,  0.999847620f);
    k.c0 = pk2( 1.475e-6f,     1.475e-6f);
    return k;
}

// Packed pair: acc += sigma(x)^2 * softplus(x) for two elements.
// Identity: sigma(x)^2 = e^{2(x - softplus(x))}  -> NO rcp, NO sign select.
// softplus(x) = max(x,0) + ln(1+u), u = e^{-|x|}, ln(1+u) via packed poly.
// Per element: 2 MUFU (ex2), ~10 issues.
__device__ __forceinline__ ull s0pair(float xa, float xb, const PC& k, ull acc) {
    const float NL2E = -1.44269504088896340736f;   // -log2(e)
    const float TL2E =  2.88539008177792681472f;   // 2*log2(e)
    float ua = ex2_a(fabsf(xa) * NL2E);            // e^{-|x|}
    float ub = ex2_a(fabsf(xb) * NL2E);
    ull U = pk2(ua, ub);
    ull P = fma2(U, k.c6, k.c5);                   // Horner, packed
    P = fma2(U, P, k.c4);
    P = fma2(U, P, k.c3);
    P = fma2(U, P, k.c2);
    P = fma2(U, P, k.c1);
    P = fma2(U, P, k.c0);                          // ln(1+u)
    ull SP = add2(pk2(fmaxf(xa, 0.0f), fmaxf(xb, 0.0f)), P);  // softplus
    float spa, spb; upk2(spa, spb, SP);
    float ta = ex2_a((xa - spa) * TL2E);           // sigma^2
    float tb = ex2_a((xb - spb) * TL2E);
    return fma2(pk2(ta, tb), SP, acc);             // acc += sigma^2 * sp
}

__device__ __forceinline__ bool lexless(float a, int ia, float b, int ib) {
    return (a < b) || (a == b && ia < ib);
}

__global__ void k_main(const float* __restrict__ locs,
                       const float* __restrict__ scores,
                       const float* __restrict__ boxes,
                       const int* __restrict__ labels,
                       float* __restrict__ out) {
    __shared__ float s_r[8];
    __shared__ float s_img[4];
    __shared__ int   s_last;

    int tid = threadIdx.x, lane = tid & 31, warp = tid >> 5;

    if (blockIdx.x >= ASSIGN_BLKS) {
        // ==== streaming S0: batch-8 independent loads, packed f32x2 math ====
        const float4* s4 = (const float4*)scores;
        const int N4  = (B_IMG * NPRI * NCLS) / 4;     // 5,456,000
        const int STR = S0_BLKS * NTHR;                // 294,912
        int sb = blockIdx.x - ASSIGN_BLKS;

        const PC k = make_pc();
        ull A0 = 0, A1 = 0, A2 = 0, A3 = 0;            // packed accumulators
        int i = sb * NTHR + tid;
        for (; i + 7 * STR < N4; i += 8 * STR) {       // 8 independent loads
            float4 v0 = s4[i];
            float4 v1 = s4[i + STR];
            float4 v2 = s4[i + 2 * STR];
            float4 v3 = s4[i + 3 * STR];
            float4 v4 = s4[i + 4 * STR];
            float4 v5 = s4[i + 5 * STR];
            float4 v6 = s4[i + 6 * STR];
            float4 v7 = s4[i + 7 * STR];
            A0 = s0pair(v0.x, v0.y, k, A0); A0 = s0pair(v0.z, v0.w, k, A0);
            A1 = s0pair(v1.x, v1.y, k, A1); A1 = s0pair(v1.z, v1.w, k, A1);
            A2 = s0pair(v2.x, v2.y, k, A2); A2 = s0pair(v2.z, v2.w, k, A2);
            A3 = s0pair(v3.x, v3.y, k, A3); A3 = s0pair(v3.z, v3.w, k, A3);
            A0 = s0pair(v4.x, v4.y, k, A0); A0 = s0pair(v4.z, v4.w, k, A0);
            A1 = s0pair(v5.x, v5.y, k, A1); A1 = s0pair(v5.z, v5.w, k, A1);
            A2 = s0pair(v6.x, v6.y, k, A2); A2 = s0pair(v6.z, v6.w, k, A2);
            A3 = s0pair(v7.x, v7.y, k, A3); A3 = s0pair(v7.z, v7.w, k, A3);
        }
        for (; i < N4; i += STR) {
            float4 v = s4[i];
            A0 = s0pair(v.x, v.y, k, A0);
            A0 = s0pair(v.z, v.w, k, A0);
        }
        float l0, h0, l1, h1, l2, h2, l3, h3;
        upk2(l0, h0, A0); upk2(l1, h1, A1);
        upk2(l2, h2, A2); upk2(l3, h3, A3);
        float acc = ((l0 + h0) + (l1 + h1)) + ((l2 + h2) + (l3 + h3));
#pragma unroll
        for (int off = 16; off; off >>= 1)
            acc += __shfl_down_sync(0xFFFFFFFFu, acc, off);
        if (lane == 0) s_r[warp] = acc;
        __syncthreads();
        if (tid == 0) {
            float t = 0.0f;
            for (int w = 0; w < 8; w++) t += s_r[w];
            g_part[sb] = 0.75f * t;
        }
    } else {
        // ================= assignment: one block per image =================
        __shared__ float s_ctab[155];
        __shared__ float s_box[KGT][4];
        __shared__ float s_gcx[KGT], s_gcy[KGT], s_area[KGT];
        __shared__ int   s_lab[KGT];
        __shared__ int   s_tidx[KGT][NSLOT];
        __shared__ float s_pov[KGT][NSLOT];
        __shared__ unsigned char s_ins[KGT][NSLOT];
        __shared__ float s_thr[KGT];
        __shared__ float s_red[2][4];

        const int   f_[5]    = {80, 40, 20, 10, 5};
        const int   coff_[5] = {0, 80, 120, 140, 150};
        const float sl_[5]   = {0.06f, 0.12f, 0.24f, 0.48f, 0.72f};
        const int   sp_[5]   = {0, 6400, 8000, 8400, 8500};

        int img = blockIdx.x;

        if (tid < KGT) {
            float x0 = boxes[(img * KGT + tid) * 4 + 0];
            float y0 = boxes[(img * KGT + tid) * 4 + 1];
            float x1 = boxes[(img * KGT + tid) * 4 + 2];
            float y1 = boxes[(img * KGT + tid) * 4 + 3];
            s_box[tid][0] = x0; s_box[tid][1] = y0; s_box[tid][2] = x1; s_box[tid][3] = y1;
            s_gcx[tid] = (x0 + x1) / 2.0f;
            s_gcy[tid] = (y0 + y1) / 2.0f;
            s_area[tid] = (x1 - x0) * (y1 - y0);
            s_lab[tid] = labels[img * KGT + tid];
        }
        // analytic priors, bit-identical to (arange+0.5)/f in fp32
        for (int t = tid; t < 155; t += NTHR) {
            int i2; float fv;
            if      (t < 80)  { i2 = t;       fv = 80.0f; }
            else if (t < 120) { i2 = t - 80;  fv = 40.0f; }
            else if (t < 140) { i2 = t - 120; fv = 20.0f; }
            else if (t < 150) { i2 = t - 140; fv = 10.0f; }
            else              { i2 = t - 150; fv = 5.0f;  }
            s_ctab[t] = ((float)i2 + 0.5f) / fv;
        }
        __syncthreads();

        // phase B: one thread per (GT, level): windowed top-9 + IoU
        if (tid < KGT * 5) {
            int k = tid / 5, l = tid - k * 5;
            int F = f_[l];
            const float* ct = s_ctab + coff_[l];
            float gcx = s_gcx[k], gcy = s_gcy[k];
            int W = (F < 6) ? F : 6;

            float ux = gcx * (float)F - 0.5f;
            int ix0 = (int)floorf(ux);
            int lx = ix0 - 2; if (lx < 0) lx = 0; if (lx > F - W) lx = F - W;
            float uy = gcy * (float)F - 0.5f;
            int iy0 = (int)floorf(uy);
            int ly = iy0 - 2; if (ly < 0) ly = 0; if (ly > F - W) ly = F - W;

            float ld[9]; int li[9];
#pragma unroll
            for (int q = 0; q < 9; q++) { ld[q] = INFINITY; li[q] = 0x7FFFFFFF; }
            for (int jy = ly; jy < ly + W; jy++) {
                float dy = gcy - ct[jy];
                for (int jx = lx; jx < lx + W; jx++) {
                    float dx = gcx - ct[jx];
                    float d  = sqrtf(dx * dx + dy * dy);
                    int p = jy * F + jx;
                    if (lexless(d, p, ld[8], li[8])) {
                        ld[8] = d; li[8] = p;
#pragma unroll
                        for (int q = 8; q > 0; q--) {
                            if (lexless(ld[q], li[q], ld[q - 1], li[q - 1])) {
                                float td = ld[q]; ld[q] = ld[q - 1]; ld[q - 1] = td;
                                int   ti = li[q]; li[q] = li[q - 1]; li[q - 1] = ti;
                            }
                        }
                    }
                }
            }
            float gx0 = s_box[k][0], gy0 = s_box[k][1];
            float gx1 = s_box[k][2], gy1 = s_box[k][3];
            float areaA = s_area[k];
            float S = sl_[l];
            float h = S / 2.0f;
#pragma unroll
            for (int j = 0; j < 9; j++) {
                int p = li[j];
                s_tidx[k][l * 9 + j] = p;
                int iy = p / F, ix = p - iy * F;
                float cx = ct[ix], cy = ct[iy];
                float px0 = cx - h, py0 = cy - h, px1 = cx + h, py1 = cy + h;
                float ltx = fmaxf(gx0, px0), lty = fmaxf(gy0, py0);
                float rbx = fminf(gx1, px1), rby = fminf(gy1, py1);
                float ww = fmaxf(rbx - ltx, 0.0f), hh = fmaxf(rby - lty, 0.0f);
                float inter = ww * hh;
                float areaB = (px1 - px0) * (py1 - py0);
                s_pov[k][l * 9 + j] = inter / (areaA + areaB - inter);
                s_ins[k][l * 9 + j] = (gx0 < cx) && (cx < gx1) && (gy0 < cy) && (cy < gy1);
            }
        }
        __syncthreads();

        // phase C: ATSS threshold per GT
        if (tid < KGT) {
            float sum = 0.0f;
            for (int t = 0; t < NSLOT; t++) sum += s_pov[tid][t];
            float mean = sum / 45.0f;
            float ss = 0.0f;
            for (int t = 0; t < NSLOT; t++) { float dv = s_pov[tid][t] - mean; ss += dv * dv; }
            s_thr[tid] = mean + sqrtf(ss / 44.0f);
        }
        __syncthreads();

        // phase D: per-slot argmax over GTs, focal correction, decode+CIoU
        float corr = 0.0f, npos = 0.0f, locv = 0.0f, vsum = 0.0f;
        if (tid < NSLOT) {
            int l = tid / 9, j = tid - l * 9;
            float best = (s_ins[0][tid] && s_pov[0][tid] > s_thr[0]) ? s_pov[0][tid] : 0.0f;
            int bk = 0;
#pragma unroll
            for (int k2 = 1; k2 < KGT; k2++) {
                float m = (s_ins[k2][tid] && s_pov[k2][tid] > s_thr[k2]) ? s_pov[k2][tid] : 0.0f;
                if (m > best) { best = m; bk = k2; }
            }
            if (best > 0.0f) {
                vsum = 1.0f;
                int lab = s_lab[bk];
                npos = 1.0f;
                int gpos = sp_[l] + j;
                float x  = scores[((long)img * NPRI + gpos) * NCLS + (lab - 1)];
                float ax = fabsf(x);
                float em = expf(-ax);
                float l1 = log1pf(em);
                float spp = fmaxf(-x, 0.0f) + l1;   // softplus(-x)
                float spn = fmaxf( x, 0.0f) + l1;   // softplus(x)
                float r  = 1.0f / (1.0f + em);
                float pp = (x >= 0.0f) ? r : em * r;
                float qq = 1.0f - pp;
                corr = 0.25f * qq * qq * spp - 0.75f * pp * pp * spn;
                int pidx = s_tidx[bk][tid];
                int gp   = sp_[l] + pidx;
                const float* g = locs + ((long)img * NPRI + gp) * 4;
                int F = f_[l]; float S = sl_[l];
                int iy = pidx / F, ix = pidx - iy * F;
                float cx = s_ctab[coff_[l] + ix], cy = s_ctab[coff_[l] + iy];
                float pcx = (g[0] * S) / 10.0f + cx;
                float pcy = (g[1] * S) / 10.0f + cy;
                float pw  = expf(g[2] / 5.0f) * S;
                float ph  = expf(g[3] / 5.0f) * S;
                float qx0 = pcx - pw / 2.0f, qy0 = pcy - ph / 2.0f;
                float qx1 = pcx + pw / 2.0f, qy1 = pcy + ph / 2.0f;
                float t0 = s_box[bk][0], t1 = s_box[bk][1];
                float t2 = s_box[bk][2], t3 = s_box[bk][3];
                float w1 = qx1 - qx0, h1 = qy1 - qy0;
                float w2 = t2 - t0,   h2 = t3 - t1;
                float ltx = fmaxf(qx0, t0), lty = fmaxf(qy0, t1);
                float rbx = fminf(qx1, t2), rby = fminf(qy1, t3);
                float iw = fmaxf(rbx - ltx, 0.0f), ih = fmaxf(rby - lty, 0.0f);
                float inter = iw * ih;
                float uni = w1 * h1 + w2 * h2 - inter;
                float iou = inter / uni;
                float c1x = (qx0 + qx1) / 2.0f, c1y = (qy0 + qy1) / 2.0f;
                float c2x = (t0 + t2) / 2.0f,  c2y = (t1 + t3) / 2.0f;
                float dx = c1x - c2x, dy = c1y - c2y;
                float rho2 = dx * dx + dy * dy;
                float ex0 = fminf(qx0, t0), ey0 = fminf(qy0, t1);
                float ex1 = fmaxf(qx1, t2), ey1 = fmaxf(qy1, t3);
                float ddx = ex1 - ex0, ddy = ey1 - ey0;
                float cdiag = ddx * ddx + ddy * ddy;
                float at = atanf(w2 / h2) - atanf(w1 / h1);
                float v  = 0.40528473456935108f * at * at;   // 4/pi^2 (fp32)
                float alpha = v / (1.0f - iou + v);
                float ci = iou - rho2 / cdiag - alpha * v;
                ci = fminf(fmaxf(ci, -1.0f), 1.0f);
                locv = 1.0f - ci;
            }
        }
        if (warp < 2) {   // slots live in warps 0 and 1 only
#pragma unroll
            for (int off = 16; off; off >>= 1) {
                corr += __shfl_down_sync(0xFFFFFFFFu, corr, off);
                npos += __shfl_down_sync(0xFFFFFFFFu, npos, off);
                locv += __shfl_down_sync(0xFFFFFFFFu, locv, off);
                vsum += __shfl_down_sync(0xFFFFFFFFu, vsum, off);
            }
            if (lane == 0) {
                s_red[warp][0] = corr; s_red[warp][1] = npos;
                s_red[warp][2] = locv; s_red[warp][3] = vsum;
            }
        }
        __syncthreads();
        if (tid == 0) {
            g_img[img][0] = s_red[0][0] + s_red[1][0];
            g_img[img][1] = s_red[0][1] + s_red[1][1];
            g_img[img][2] = s_red[0][2] + s_red[1][2];
            g_img[img][3] = s_red[0][3] + s_red[1][3];
        }
    }

    // ---- last-block-done: deterministic fixed-order final reduction ----
    __threadfence();
    __syncthreads();
    if (tid == 0) {
        unsigned int v = atomicAdd(&g_done, 1u);
        s_last = (v == NBLK_TOT - 1) ? 1 : 0;
    }
    __syncthreads();
    if (s_last) {
        __threadfence();
        float acc2 = 0.0f;
        for (int j = tid; j < S0_BLKS; j += NTHR) acc2 += g_part[j];
#pragma unroll
        for (int off = 16; off; off >>= 1)
            acc2 += __shfl_down_sync(0xFFFFFFFFu, acc2, off);
        if (lane == 0) s_r[warp] = acc2;
        if (warp == 1) {   // reduce the 32 per-image 4-vectors (fixed order)
            float c0 = g_img[lane][0], c1 = g_img[lane][1];
            float c2 = g_img[lane][2], c3 = g_img[lane][3];
#pragma unroll
            for (int off = 16; off; off >>= 1) {
                c0 += __shfl_down_sync(0xFFFFFFFFu, c0, off);
                c1 += __shfl_down_sync(0xFFFFFFFFu, c1, off);
                c2 += __shfl_down_sync(0xFFFFFFFFu, c2, off);
                c3 += __shfl_down_sync(0xFFFFFFFFu, c3, off);
            }
            if (lane == 0) {
                s_img[0] = c0; s_img[1] = c1; s_img[2] = c2; s_img[3] = c3;
            }
        }
        __syncthreads();
        if (tid == 0) {
            float s0 = 0.0f;
            for (int w = 0; w < 8; w++) s0 += s_r[w];
            float conf = (s0 + s_img[0]) / s_img[1];
            float loc  = s_img[2] / fmaxf(s_img[3], 1.0f);
            out[0] = conf + loc;
            g_done = 0;   // self-reset for next graph replay
        }
    }
}

extern "C" void kernel_launch(void* const* d_in, const int* in_sizes, int n_in,
                              void* d_out, int out_size) {
    const float* locs   = (const float*)d_in[0];
    const float* scores = (const float*)d_in[1];
    const float* boxes  = (const float*)d_in[2];
    const int*   labels = (const int*)d_in[3];
    float* out = (float*)d_out;
    (void)in_sizes; (void)n_in; (void)out_size;

    k_main<<<NBLK_TOT, NTHR>>>(locs, scores, boxes, labels, out);
}